// round 10
// baseline (speedup 1.0000x reference)
// CrossLayerTranscoder — tf32 mma.sync GEMM. R10 = R9 fixed: padded 144B-row
// SMEM layout (no XOR swizzle) so every fragment LDS address is base_reg +
// compile-time constant -> ptxas folds into LDS [r+imm], zero per-access ALU.
// (R9 failed to build: unroll var can't be a template arg; plain adds fold fine.)
// Conflict-free: fragment banks = c0 + 4*r8 + t (32 distinct); producer octet =
// one row x 8 chunks (distinct 16B quads).
//
// encode: feats[l] = relu(resid[l] @ enc_w[l]^T)            M=2048,N=512,K=2048
// decode: recon[t] = sum_{s<=t} feats[s] @ dec_w[s,t]^T     M=2048,N=2048,K=(t+1)*512
//
// CTA 128x128x32, 3-stage cp.async, 128 threads (2 CTAs/SM), 4 warps of 64x64.

#include <cuda_runtime.h>
#include <cstdint>
#include <cstddef>

#define L_DIM 16
#define BS_DIM 2048
#define H_DIM 2048
#define F_DIM 512

#define TM 128
#define TN 128
#define TK 32
#define STAGES 3
#define NTHREADS 128

#define ROW_BYTES 144                        // 36 floats: pad kills conflicts
#define TILE_BYTES (TM * ROW_BYTES)          // 18432
#define STAGE_BYTES (2 * TILE_BYTES)         // 36864
#define SMEM_BYTES (STAGES * STAGE_BYTES)    // 110592 (x2 CTAs = 216 KB)

__device__ __forceinline__ uint32_t smem_u32(const void* p) {
    uint32_t a;
    asm("{ .reg .u64 t; cvta.to.shared.u64 t, %1; cvt.u32.u64 %0, t; }" : "=r"(a) : "l"(p));
    return a;
}
__device__ __forceinline__ void cp_async16(uint32_t dst, const float* src) {
    asm volatile("cp.async.cg.shared.global [%0], [%1], 16;" :: "r"(dst), "l"(src));
}
__device__ __forceinline__ void cp_commit() { asm volatile("cp.async.commit_group;"); }
template <int N> __device__ __forceinline__ void cp_wait() {
    asm volatile("cp.async.wait_group %0;" :: "n"(N));
}
// LDS + RNA convert; address is base_reg + folded constant -> LDS [r+imm]
__device__ __forceinline__ uint32_t ldtf32(uint32_t addr) {
    float v; uint32_t r;
    asm volatile("ld.shared.f32 %0, [%1];" : "=f"(v) : "r"(addr));
    asm("cvt.rna.tf32.f32 %0, %1;" : "=r"(r) : "f"(v));
    return r;
}
__device__ __forceinline__ void mma_tf32(float* c, const uint32_t* a, const uint32_t* b) {
    asm volatile(
        "mma.sync.aligned.m16n8k8.row.col.f32.tf32.tf32.f32 "
        "{%0,%1,%2,%3}, {%4,%5,%6,%7}, {%8,%9}, {%0,%1,%2,%3};"
        : "+f"(c[0]), "+f"(c[1]), "+f"(c[2]), "+f"(c[3])
        : "r"(a[0]), "r"(a[1]), "r"(a[2]), "r"(a[3]), "r"(b[0]), "r"(b[1]));
}

template <bool ENCODE>
__global__ __launch_bounds__(NTHREADS, 2)
void clt_gemm(const float* __restrict__ gA, const float* __restrict__ gB,
              float* __restrict__ gOut) {
    extern __shared__ float smem[];
    const uint32_t sbase = smem_u32(smem);
    const int tid  = threadIdx.x;
    const int lane = tid & 31;
    const int w    = tid >> 5;
    const int wm   = w & 1;        // 2 warps along M (64 rows)
    const int wn   = w >> 1;       // 2 warps along N (64 cols)
    const int r8   = lane >> 2;
    const int t    = lane & 3;
    const int m0   = blockIdx.x * TM;
    const int n0   = blockIdx.y * TN;
    const int z    = (int)gridDim.z - 1 - (int)blockIdx.z;   // heavy z first
    const int iters = ENCODE ? (H_DIM / TK) : ((z + 1) * (F_DIM / TK));
    const int LD   = ENCODE ? H_DIM : F_DIM;   // compile-time row pitch

    float acc[4][8][4];
    #pragma unroll
    for (int mt = 0; mt < 4; mt++)
        #pragma unroll
        for (int nt = 0; nt < 8; nt++)
            #pragma unroll
            for (int r = 0; r < 4; r++) acc[mt][nt][r] = 0.0f;

    // ---------- producer pointers (incremental, coalesced mapping) ----------
    // chunk q = j*128 + tid: row = j*16 + (tid>>3), chunk col = tid&7.
    // Warp octet = one row x 8 chunks -> full 128B global lines, distinct 16B
    // SMEM quads (conflict-free cp.async stores).
    const int tid8 = tid >> 3;
    const int cch  = tid & 7;
    const float* pA;
    const float* pB;
    if (ENCODE) {
        pA = gA + ((size_t)z * BS_DIM + m0 + tid8) * H_DIM + cch * 4;
        pB = gB + ((size_t)z * F_DIM + n0 + tid8) * H_DIM + cch * 4;
    } else {
        pA = gA + (size_t)(m0 + tid8) * F_DIM + cch * 4;               // feats[0]
        pB = gB + ((size_t)z * H_DIM + n0 + tid8) * F_DIM + cch * 4;   // dec_w[0][z]
    }
    const uint32_t dst0 = (uint32_t)tid8 * ROW_BYTES + (uint32_t)cch * 16;
    int fi = 0;
    auto load_stage = [&]() {
        const int slot = fi % STAGES;
        uint32_t dA = sbase + (uint32_t)slot * STAGE_BYTES + dst0;
        uint32_t dB = dA + TILE_BYTES;
        #pragma unroll
        for (int j = 0; j < 8; j++)
            cp_async16(dA + (uint32_t)j * (16 * ROW_BYTES), pA + (size_t)j * 16 * LD);
        #pragma unroll
        for (int j = 0; j < 8; j++)
            cp_async16(dB + (uint32_t)j * (16 * ROW_BYTES), pB + (size_t)j * 16 * LD);
        cp_commit();
        if (ENCODE) { pA += TK; pB += TK; }
        else {
            bool roll = (fi & 15) == 15;   // advance source layer s
            pA += roll ? ((size_t)BS_DIM * F_DIM - 15 * TK) : TK;
            pB += roll ? ((size_t)L_DIM * H_DIM * F_DIM - 15 * TK) : TK;
        }
        fi++;
    };

    // ---------- per-thread fragment base offsets (within tile, bytes) ----------
    const uint32_t rowA = (uint32_t)(wm * 64 + r8) * ROW_BYTES + (uint32_t)t * 4;
    const uint32_t rowB = (uint32_t)(wn * 64 + r8) * ROW_BYTES + (uint32_t)t * 4;

    // ---------- prologue ----------
    load_stage();
    load_stage();

    // ---------- mainloop: one barrier per iteration ----------
    for (int i = 0; i < iters; i++) {
        cp_wait<STAGES - 2>();
        __syncthreads();
        if (fi < iters) load_stage();

        const uint32_t aslot = sbase + (uint32_t)(i % STAGES) * STAGE_BYTES;
        const uint32_t abase = aslot + rowA;
        const uint32_t bbase = aslot + TILE_BYTES + rowB;

        #pragma unroll
        for (int ks = 0; ks < 4; ks++) {
            uint32_t af[4][4], bf[8][2];
            // all offsets are unrolled constants -> ptxas folds into LDS [r+imm]
            #pragma unroll
            for (int mt = 0; mt < 4; mt++) {
                af[mt][0] = ldtf32(abase + (uint32_t)(mt * 2304 +        ks * 32));
                af[mt][1] = ldtf32(abase + (uint32_t)(mt * 2304 + 1152 + ks * 32));
                af[mt][2] = ldtf32(abase + (uint32_t)(mt * 2304 +        ks * 32 + 16));
                af[mt][3] = ldtf32(abase + (uint32_t)(mt * 2304 + 1152 + ks * 32 + 16));
            }
            #pragma unroll
            for (int nt = 0; nt < 8; nt++) {
                bf[nt][0] = ldtf32(bbase + (uint32_t)(nt * 1152 + ks * 32));
                bf[nt][1] = ldtf32(bbase + (uint32_t)(nt * 1152 + ks * 32 + 16));
            }
            #pragma unroll
            for (int mt = 0; mt < 4; mt++)
                #pragma unroll
                for (int nt = 0; nt < 8; nt++)
                    mma_tf32(acc[mt][nt], af[mt], bf[nt]);
        }
    }

    // ---------- epilogue: direct float2 stores ----------
    const int ldo = ENCODE ? F_DIM : H_DIM;
    float* ob = gOut + (size_t)z * BS_DIM * ldo;
    #pragma unroll
    for (int mt = 0; mt < 4; mt++) {
        #pragma unroll
        for (int nt = 0; nt < 8; nt++) {
            int row = m0 + wm * 64 + mt * 16 + r8;
            int col = n0 + wn * 64 + nt * 8 + t * 2;
            float v0 = acc[mt][nt][0], v1 = acc[mt][nt][1];
            float v2 = acc[mt][nt][2], v3 = acc[mt][nt][3];
            if (ENCODE) {
                v0 = fmaxf(v0, 0.0f); v1 = fmaxf(v1, 0.0f);
                v2 = fmaxf(v2, 0.0f); v3 = fmaxf(v3, 0.0f);
            }
            *(float2*)&ob[(size_t)row * ldo + col]       = make_float2(v0, v1);
            *(float2*)&ob[(size_t)(row + 8) * ldo + col] = make_float2(v2, v3);
        }
    }
}

extern "C" void kernel_launch(void* const* d_in, const int* in_sizes, int n_in,
                              void* d_out, int out_size) {
    (void)in_sizes; (void)n_in; (void)out_size;
    const float* resid = (const float*)d_in[0];   // [L, B, S, H]
    const float* enc_w = (const float*)d_in[1];   // [L, F, H]
    const float* dec_w = (const float*)d_in[2];   // [L, L, H, F]
    float* out   = (float*)d_out;
    float* feats = out;                                   // [L, BS, F]
    float* recon = out + (size_t)L_DIM * BS_DIM * F_DIM;  // [L, BS, H]

    cudaFuncSetAttribute(clt_gemm<true>,  cudaFuncAttributeMaxDynamicSharedMemorySize, SMEM_BYTES);
    cudaFuncSetAttribute(clt_gemm<false>, cudaFuncAttributeMaxDynamicSharedMemorySize, SMEM_BYTES);

    dim3 grid_enc(BS_DIM / TM, F_DIM / TN, L_DIM);   // 16 x 4 x 16
    clt_gemm<true><<<grid_enc, NTHREADS, SMEM_BYTES>>>(resid, enc_w, feats);

    dim3 grid_dec(BS_DIM / TM, H_DIM / TN, L_DIM);   // 16 x 16 x 16
    clt_gemm<false><<<grid_dec, NTHREADS, SMEM_BYTES>>>(feats, dec_w, recon);
}

// round 11
// speedup vs baseline: 1.0110x; 1.0110x over previous
// CrossLayerTranscoder — tf32 mma.sync GEMM. R11 = padded 144B-row layout
// (zero per-access address ALU, from R10) + explicit ks-level fragment double
// buffering (forced prefetch distance, from R8). R10 showed ptxas tightens the
// schedule when registers get cheap, exposing LDS latency; the double buffer
// structurally guarantees a 32-MMA shadow over every fragment load.
//
// encode: feats[l] = relu(resid[l] @ enc_w[l]^T)            M=2048,N=512,K=2048
// decode: recon[t] = sum_{s<=t} feats[s] @ dec_w[s,t]^T     M=2048,N=2048,K=(t+1)*512
//
// CTA 128x128x32, 3-stage cp.async, 128 threads (2 CTAs/SM), 4 warps of 64x64.

#include <cuda_runtime.h>
#include <cstdint>
#include <cstddef>

#define L_DIM 16
#define BS_DIM 2048
#define H_DIM 2048
#define F_DIM 512

#define TM 128
#define TN 128
#define TK 32
#define STAGES 3
#define NTHREADS 128

#define ROW_BYTES 144                        // 36 floats: padding kills conflicts
#define TILE_BYTES (TM * ROW_BYTES)          // 18432
#define STAGE_BYTES (2 * TILE_BYTES)         // 36864
#define SMEM_BYTES (STAGES * STAGE_BYTES)    // 110592 (x2 CTAs = 216 KB)

__device__ __forceinline__ uint32_t smem_u32(const void* p) {
    uint32_t a;
    asm("{ .reg .u64 t; cvta.to.shared.u64 t, %1; cvt.u32.u64 %0, t; }" : "=r"(a) : "l"(p));
    return a;
}
__device__ __forceinline__ void cp_async16(uint32_t dst, const float* src) {
    asm volatile("cp.async.cg.shared.global [%0], [%1], 16;" :: "r"(dst), "l"(src));
}
__device__ __forceinline__ void cp_commit() { asm volatile("cp.async.commit_group;"); }
template <int N> __device__ __forceinline__ void cp_wait() {
    asm volatile("cp.async.wait_group %0;" :: "n"(N));
}
// LDS + RNA convert; address = base_reg + folded constant -> LDS [r+imm]
__device__ __forceinline__ uint32_t ldtf32(uint32_t addr) {
    float v; uint32_t r;
    asm volatile("ld.shared.f32 %0, [%1];" : "=f"(v) : "r"(addr));
    asm("cvt.rna.tf32.f32 %0, %1;" : "=r"(r) : "f"(v));
    return r;
}
__device__ __forceinline__ void mma_tf32(float* c, const uint32_t* a, const uint32_t* b) {
    asm volatile(
        "mma.sync.aligned.m16n8k8.row.col.f32.tf32.tf32.f32 "
        "{%0,%1,%2,%3}, {%4,%5,%6,%7}, {%8,%9}, {%0,%1,%2,%3};"
        : "+f"(c[0]), "+f"(c[1]), "+f"(c[2]), "+f"(c[3])
        : "r"(a[0]), "r"(a[1]), "r"(a[2]), "r"(a[3]), "r"(b[0]), "r"(b[1]));
}

template <bool ENCODE>
__global__ __launch_bounds__(NTHREADS, 2)
void clt_gemm(const float* __restrict__ gA, const float* __restrict__ gB,
              float* __restrict__ gOut) {
    extern __shared__ float smem[];
    const uint32_t sbase = smem_u32(smem);
    const int tid  = threadIdx.x;
    const int lane = tid & 31;
    const int w    = tid >> 5;
    const int wm   = w & 1;        // 2 warps along M (64 rows)
    const int wn   = w >> 1;       // 2 warps along N (64 cols)
    const int r8   = lane >> 2;
    const int t    = lane & 3;
    const int m0   = blockIdx.x * TM;
    const int n0   = blockIdx.y * TN;
    const int z    = (int)gridDim.z - 1 - (int)blockIdx.z;   // heavy z first
    const int iters = ENCODE ? (H_DIM / TK) : ((z + 1) * (F_DIM / TK));
    const int LD   = ENCODE ? H_DIM : F_DIM;   // compile-time row pitch

    float acc[4][8][4];
    #pragma unroll
    for (int mt = 0; mt < 4; mt++)
        #pragma unroll
        for (int nt = 0; nt < 8; nt++)
            #pragma unroll
            for (int r = 0; r < 4; r++) acc[mt][nt][r] = 0.0f;

    // ---------- producer pointers (incremental, coalesced mapping) ----------
    // chunk q = j*128 + tid: row = j*16 + (tid>>3), chunk col = tid&7.
    // Warp octet = one row x 8 chunks -> full 128B global lines; SMEM quads
    // (tid8+cch) mod 8 evenly distributed -> conflict-free stores.
    const int tid8 = tid >> 3;
    const int cch  = tid & 7;
    const float* pA;
    const float* pB;
    if (ENCODE) {
        pA = gA + ((size_t)z * BS_DIM + m0 + tid8) * H_DIM + cch * 4;
        pB = gB + ((size_t)z * F_DIM + n0 + tid8) * H_DIM + cch * 4;
    } else {
        pA = gA + (size_t)(m0 + tid8) * F_DIM + cch * 4;               // feats[0]
        pB = gB + ((size_t)z * H_DIM + n0 + tid8) * F_DIM + cch * 4;   // dec_w[0][z]
    }
    const uint32_t dst0 = (uint32_t)tid8 * ROW_BYTES + (uint32_t)cch * 16;
    int fi = 0;
    auto load_stage = [&]() {
        const int slot = fi % STAGES;
        uint32_t dA = sbase + (uint32_t)slot * STAGE_BYTES + dst0;
        uint32_t dB = dA + TILE_BYTES;
        #pragma unroll
        for (int j = 0; j < 8; j++)
            cp_async16(dA + (uint32_t)j * (16 * ROW_BYTES), pA + (size_t)j * 16 * LD);
        #pragma unroll
        for (int j = 0; j < 8; j++)
            cp_async16(dB + (uint32_t)j * (16 * ROW_BYTES), pB + (size_t)j * 16 * LD);
        cp_commit();
        if (ENCODE) { pA += TK; pB += TK; }
        else {
            bool roll = (fi & 15) == 15;   // advance source layer s
            pA += roll ? ((size_t)BS_DIM * F_DIM - 15 * TK) : TK;
            pB += roll ? ((size_t)L_DIM * H_DIM * F_DIM - 15 * TK) : TK;
        }
        fi++;
    };

    // ---------- per-thread fragment base offsets (within tile, bytes) ----------
    // bank = (4*r8 + t) mod 32: distinct across the warp -> conflict-free LDS.
    const uint32_t rowA = (uint32_t)(wm * 64 + r8) * ROW_BYTES + (uint32_t)t * 4;
    const uint32_t rowB = (uint32_t)(wn * 64 + r8) * ROW_BYTES + (uint32_t)t * 4;

    // ---------- prologue ----------
    load_stage();
    load_stage();

    // ---------- mainloop: ks double-buffered fragments, one barrier/iter ----------
    uint32_t af[2][4][4], bf[2][8][2];
    for (int i = 0; i < iters; i++) {
        cp_wait<STAGES - 2>();
        __syncthreads();
        if (fi < iters) load_stage();

        const uint32_t aslot = sbase + (uint32_t)(i % STAGES) * STAGE_BYTES;
        const uint32_t abase = aslot + rowA;
        const uint32_t bbase = aslot + TILE_BYTES + rowB;

        // fragment loader for k-step ks into buffer cb (offsets fold to imm)
        auto ldfrag = [&](int ks, int cb) {
            #pragma unroll
            for (int mt = 0; mt < 4; mt++) {
                af[cb][mt][0] = ldtf32(abase + (uint32_t)(mt * 2304 +        ks * 32));
                af[cb][mt][1] = ldtf32(abase + (uint32_t)(mt * 2304 + 1152 + ks * 32));
                af[cb][mt][2] = ldtf32(abase + (uint32_t)(mt * 2304 +        ks * 32 + 16));
                af[cb][mt][3] = ldtf32(abase + (uint32_t)(mt * 2304 + 1152 + ks * 32 + 16));
            }
            #pragma unroll
            for (int nt = 0; nt < 8; nt++) {
                bf[cb][nt][0] = ldtf32(bbase + (uint32_t)(nt * 1152 + ks * 32));
                bf[cb][nt][1] = ldtf32(bbase + (uint32_t)(nt * 1152 + ks * 32 + 16));
            }
        };

        ldfrag(0, 0);
        #pragma unroll
        for (int ks = 0; ks < 4; ks++) {
            const int cb = ks & 1;
            if (ks < 3) ldfrag(ks + 1, cb ^ 1);   // loads shadowed by 32 MMAs below
            #pragma unroll
            for (int mt = 0; mt < 4; mt++)
                #pragma unroll
                for (int nt = 0; nt < 8; nt++)
                    mma_tf32(acc[mt][nt], af[cb][mt], bf[cb][nt]);
        }
    }

    // ---------- epilogue: direct float2 stores ----------
    const int ldo = ENCODE ? F_DIM : H_DIM;
    float* ob = gOut + (size_t)z * BS_DIM * ldo;
    #pragma unroll
    for (int mt = 0; mt < 4; mt++) {
        #pragma unroll
        for (int nt = 0; nt < 8; nt++) {
            int row = m0 + wm * 64 + mt * 16 + r8;
            int col = n0 + wn * 64 + nt * 8 + t * 2;
            float v0 = acc[mt][nt][0], v1 = acc[mt][nt][1];
            float v2 = acc[mt][nt][2], v3 = acc[mt][nt][3];
            if (ENCODE) {
                v0 = fmaxf(v0, 0.0f); v1 = fmaxf(v1, 0.0f);
                v2 = fmaxf(v2, 0.0f); v3 = fmaxf(v3, 0.0f);
            }
            *(float2*)&ob[(size_t)row * ldo + col]       = make_float2(v0, v1);
            *(float2*)&ob[(size_t)(row + 8) * ldo + col] = make_float2(v2, v3);
        }
    }
}

extern "C" void kernel_launch(void* const* d_in, const int* in_sizes, int n_in,
                              void* d_out, int out_size) {
    (void)in_sizes; (void)n_in; (void)out_size;
    const float* resid = (const float*)d_in[0];   // [L, B, S, H]
    const float* enc_w = (const float*)d_in[1];   // [L, F, H]
    const float* dec_w = (const float*)d_in[2];   // [L, L, H, F]
    float* out   = (float*)d_out;
    float* feats = out;                                   // [L, BS, F]
    float* recon = out + (size_t)L_DIM * BS_DIM * F_DIM;  // [L, BS, H]

    cudaFuncSetAttribute(clt_gemm<true>,  cudaFuncAttributeMaxDynamicSharedMemorySize, SMEM_BYTES);
    cudaFuncSetAttribute(clt_gemm<false>, cudaFuncAttributeMaxDynamicSharedMemorySize, SMEM_BYTES);

    dim3 grid_enc(BS_DIM / TM, F_DIM / TN, L_DIM);   // 16 x 4 x 16
    clt_gemm<true><<<grid_enc, NTHREADS, SMEM_BYTES>>>(resid, enc_w, feats);

    dim3 grid_dec(BS_DIM / TM, H_DIM / TN, L_DIM);   // 16 x 16 x 16
    clt_gemm<false><<<grid_dec, NTHREADS, SMEM_BYTES>>>(feats, dec_w, recon);
}

// round 12
// speedup vs baseline: 1.1274x; 1.1152x over previous
// CrossLayerTranscoder — tf32 mma.sync GEMM. R12: 3 CTAs/SM (12 warps, 3/SMSP)
// to cover LDS->CVT->MMA dependency stalls with TLP — R8/R10/R11 proved the
// limiter is 2 warps/SMSP stalling together, not instruction count or ILP
// scheduling. Padded 144B layout (low instr+regs) + 2-stage cp.async (72KB/CTA,
// x3 = 216KB) makes the residency fit. Two barriers/iter (2-stage correctness).
//
// encode: feats[l] = relu(resid[l] @ enc_w[l]^T)            M=2048,N=512,K=2048
// decode: recon[t] = sum_{s<=t} feats[s] @ dec_w[s,t]^T     M=2048,N=2048,K=(t+1)*512
//
// CTA 128x128x32, 128 threads, 4 warps of 64x64.

#include <cuda_runtime.h>
#include <cstdint>
#include <cstddef>

#define L_DIM 16
#define BS_DIM 2048
#define H_DIM 2048
#define F_DIM 512

#define TM 128
#define TN 128
#define TK 32
#define STAGES 2
#define NTHREADS 128

#define ROW_BYTES 144                        // 36 floats: padding kills conflicts
#define TILE_BYTES (TM * ROW_BYTES)          // 18432
#define STAGE_BYTES (2 * TILE_BYTES)         // 36864
#define SMEM_BYTES (STAGES * STAGE_BYTES)    // 73728 (x3 CTAs = 216 KB)

__device__ __forceinline__ uint32_t smem_u32(const void* p) {
    uint32_t a;
    asm("{ .reg .u64 t; cvta.to.shared.u64 t, %1; cvt.u32.u64 %0, t; }" : "=r"(a) : "l"(p));
    return a;
}
__device__ __forceinline__ void cp_async16(uint32_t dst, const float* src) {
    asm volatile("cp.async.cg.shared.global [%0], [%1], 16;" :: "r"(dst), "l"(src));
}
__device__ __forceinline__ void cp_commit() { asm volatile("cp.async.commit_group;"); }
template <int N> __device__ __forceinline__ void cp_wait() {
    asm volatile("cp.async.wait_group %0;" :: "n"(N));
}
// LDS + RNA convert; address = base_reg + folded constant -> LDS [r+imm]
__device__ __forceinline__ uint32_t ldtf32(uint32_t addr) {
    float v; uint32_t r;
    asm volatile("ld.shared.f32 %0, [%1];" : "=f"(v) : "r"(addr));
    asm("cvt.rna.tf32.f32 %0, %1;" : "=r"(r) : "f"(v));
    return r;
}
__device__ __forceinline__ void mma_tf32(float* c, const uint32_t* a, const uint32_t* b) {
    asm volatile(
        "mma.sync.aligned.m16n8k8.row.col.f32.tf32.tf32.f32 "
        "{%0,%1,%2,%3}, {%4,%5,%6,%7}, {%8,%9}, {%0,%1,%2,%3};"
        : "+f"(c[0]), "+f"(c[1]), "+f"(c[2]), "+f"(c[3])
        : "r"(a[0]), "r"(a[1]), "r"(a[2]), "r"(a[3]), "r"(b[0]), "r"(b[1]));
}

template <bool ENCODE>
__global__ __launch_bounds__(NTHREADS, 3)
void clt_gemm(const float* __restrict__ gA, const float* __restrict__ gB,
              float* __restrict__ gOut) {
    extern __shared__ float smem[];
    const uint32_t sbase = smem_u32(smem);
    const int tid  = threadIdx.x;
    const int lane = tid & 31;
    const int w    = tid >> 5;
    const int wm   = w & 1;        // 2 warps along M (64 rows)
    const int wn   = w >> 1;       // 2 warps along N (64 cols)
    const int r8   = lane >> 2;
    const int t    = lane & 3;
    const int m0   = blockIdx.x * TM;
    const int n0   = blockIdx.y * TN;
    const int z    = (int)gridDim.z - 1 - (int)blockIdx.z;   // heavy z first
    const int iters = ENCODE ? (H_DIM / TK) : ((z + 1) * (F_DIM / TK));
    const int LD   = ENCODE ? H_DIM : F_DIM;   // compile-time row pitch

    float acc[4][8][4];
    #pragma unroll
    for (int mt = 0; mt < 4; mt++)
        #pragma unroll
        for (int nt = 0; nt < 8; nt++)
            #pragma unroll
            for (int r = 0; r < 4; r++) acc[mt][nt][r] = 0.0f;

    // ---------- producer pointers (incremental, coalesced mapping) ----------
    // chunk q = j*128 + tid: row = j*16 + (tid>>3), chunk col = tid&7.
    // Warp octet = one row x 8 chunks -> full 128B global lines.
    const int tid8 = tid >> 3;
    const int cch  = tid & 7;
    const float* pA;
    const float* pB;
    if (ENCODE) {
        pA = gA + ((size_t)z * BS_DIM + m0 + tid8) * H_DIM + cch * 4;
        pB = gB + ((size_t)z * F_DIM + n0 + tid8) * H_DIM + cch * 4;
    } else {
        pA = gA + (size_t)(m0 + tid8) * F_DIM + cch * 4;               // feats[0]
        pB = gB + ((size_t)z * H_DIM + n0 + tid8) * F_DIM + cch * 4;   // dec_w[0][z]
    }
    const uint32_t dst0 = (uint32_t)tid8 * ROW_BYTES + (uint32_t)cch * 16;
    int fi = 0;
    auto load_stage = [&]() {
        const int slot = fi & 1;
        uint32_t dA = sbase + (uint32_t)slot * STAGE_BYTES + dst0;
        uint32_t dB = dA + TILE_BYTES;
        #pragma unroll
        for (int j = 0; j < 8; j++)
            cp_async16(dA + (uint32_t)j * (16 * ROW_BYTES), pA + (size_t)j * 16 * LD);
        #pragma unroll
        for (int j = 0; j < 8; j++)
            cp_async16(dB + (uint32_t)j * (16 * ROW_BYTES), pB + (size_t)j * 16 * LD);
        cp_commit();
        if (ENCODE) { pA += TK; pB += TK; }
        else {
            bool roll = (fi & 15) == 15;   // advance source layer s
            pA += roll ? ((size_t)BS_DIM * F_DIM - 15 * TK) : TK;
            pB += roll ? ((size_t)L_DIM * H_DIM * F_DIM - 15 * TK) : TK;
        }
        fi++;
    };

    // ---------- per-thread fragment base offsets (within tile, bytes) ----------
    // bank = (4*r8 + t) mod 32: distinct across the warp -> conflict-free LDS.
    const uint32_t rowA = (uint32_t)(wm * 64 + r8) * ROW_BYTES + (uint32_t)t * 4;
    const uint32_t rowB = (uint32_t)(wn * 64 + r8) * ROW_BYTES + (uint32_t)t * 4;

    // ---------- prologue: fill both stages ----------
    load_stage();
    load_stage();

    // ---------- mainloop (2-stage, 2 barriers/iter) ----------
    // order per iter: wait(stage i ready) | barrier | compute(i) | barrier |
    // load(i+2) into the slot just freed. load(i+2) overlaps compute(i+1).
    for (int i = 0; i < iters; i++) {
        cp_wait<1>();
        __syncthreads();   // stage i visible to every warp

        const uint32_t aslot = sbase + (uint32_t)(i & 1) * STAGE_BYTES;
        const uint32_t abase = aslot + rowA;
        const uint32_t bbase = aslot + TILE_BYTES + rowB;

        #pragma unroll
        for (int ks = 0; ks < 4; ks++) {
            uint32_t af[4][4], bf[8][2];
            #pragma unroll
            for (int mt = 0; mt < 4; mt++) {
                af[mt][0] = ldtf32(abase + (uint32_t)(mt * 2304 +        ks * 32));
                af[mt][1] = ldtf32(abase + (uint32_t)(mt * 2304 + 1152 + ks * 32));
                af[mt][2] = ldtf32(abase + (uint32_t)(mt * 2304 +        ks * 32 + 16));
                af[mt][3] = ldtf32(abase + (uint32_t)(mt * 2304 + 1152 + ks * 32 + 16));
            }
            #pragma unroll
            for (int nt = 0; nt < 8; nt++) {
                bf[nt][0] = ldtf32(bbase + (uint32_t)(nt * 1152 + ks * 32));
                bf[nt][1] = ldtf32(bbase + (uint32_t)(nt * 1152 + ks * 32 + 16));
            }
            #pragma unroll
            for (int mt = 0; mt < 4; mt++)
                #pragma unroll
                for (int nt = 0; nt < 8; nt++)
                    mma_tf32(acc[mt][nt], af[mt], bf[nt]);
        }

        __syncthreads();   // all warps done reading stage i
        if (fi < iters) load_stage();   // refill freed slot; overlaps next compute
    }

    // ---------- epilogue: direct float2 stores ----------
    const int ldo = ENCODE ? F_DIM : H_DIM;
    float* ob = gOut + (size_t)z * BS_DIM * ldo;
    #pragma unroll
    for (int mt = 0; mt < 4; mt++) {
        #pragma unroll
        for (int nt = 0; nt < 8; nt++) {
            int row = m0 + wm * 64 + mt * 16 + r8;
            int col = n0 + wn * 64 + nt * 8 + t * 2;
            float v0 = acc[mt][nt][0], v1 = acc[mt][nt][1];
            float v2 = acc[mt][nt][2], v3 = acc[mt][nt][3];
            if (ENCODE) {
                v0 = fmaxf(v0, 0.0f); v1 = fmaxf(v1, 0.0f);
                v2 = fmaxf(v2, 0.0f); v3 = fmaxf(v3, 0.0f);
            }
            *(float2*)&ob[(size_t)row * ldo + col]       = make_float2(v0, v1);
            *(float2*)&ob[(size_t)(row + 8) * ldo + col] = make_float2(v2, v3);
        }
    }
}

extern "C" void kernel_launch(void* const* d_in, const int* in_sizes, int n_in,
                              void* d_out, int out_size) {
    (void)in_sizes; (void)n_in; (void)out_size;
    const float* resid = (const float*)d_in[0];   // [L, B, S, H]
    const float* enc_w = (const float*)d_in[1];   // [L, F, H]
    const float* dec_w = (const float*)d_in[2];   // [L, L, H, F]
    float* out   = (float*)d_out;
    float* feats = out;                                   // [L, BS, F]
    float* recon = out + (size_t)L_DIM * BS_DIM * F_DIM;  // [L, BS, H]

    cudaFuncSetAttribute(clt_gemm<true>,  cudaFuncAttributeMaxDynamicSharedMemorySize, SMEM_BYTES);
    cudaFuncSetAttribute(clt_gemm<false>, cudaFuncAttributeMaxDynamicSharedMemorySize, SMEM_BYTES);

    dim3 grid_enc(BS_DIM / TM, F_DIM / TN, L_DIM);   // 16 x 4 x 16
    clt_gemm<true><<<grid_enc, NTHREADS, SMEM_BYTES>>>(resid, enc_w, feats);

    dim3 grid_dec(BS_DIM / TM, H_DIM / TN, L_DIM);   // 16 x 16 x 16
    clt_gemm<false><<<grid_dec, NTHREADS, SMEM_BYTES>>>(feats, dec_w, recon);
}